// round 10
// baseline (speedup 1.0000x reference)
#include <cuda_runtime.h>
#include <cuda_fp16.h>
#include <cstdint>

// Shape: x [B=4, S=2048, D=1024] fp32; Wq/Wk/Wv [D, D] fp32 (y = x @ W^T)
#define BATCH 4
#define SEQ   2048
#define DM    1024
#define MTOT  (BATCH * SEQ)   // 8192

__device__ __half g_X[MTOT * DM];
__device__ __half g_W[3 * DM * DM];
__device__ __half g_Q[MTOT * DM];
__device__ __half g_K[MTOT * DM];
__device__ __half g_V[MTOT * DM];
__device__ float  g_P[(long)MTOT * SEQ];    // fp32 scores
__device__ __half g_Ph[(long)MTOT * SEQ];   // fp16 probs

// ---------------------------------------------------------------------------
// FP16 mma.sync (m16n8k16) GEMM, cp.async 3-stage, BK=64 halves.
// Block tile 128x256, 8 warps (2x4), warp tile 64x64.
// A tile: 128 rows x 128B, xor swizzle (chunk ^= row&7).
// B_NK tile: 256 rows x 128B, same swizzle.
// B_KN tile (V): 64 k-rows x 512B (32 chunks), same swizzle, ldmatrix.trans.
// ---------------------------------------------------------------------------
#define BM 128
#define BN 256
#define TBK 64
#define STAGES 3
#define A_STAGE 16384
#define B_STAGE 32768
#define STAGE   (A_STAGE + B_STAGE)
#define DYN_BYTES (STAGES * STAGE + 256)

__device__ __forceinline__ uint32_t smem_u32(const void* p) {
    uint32_t a;
    asm("{ .reg .u64 t; cvta.to.shared.u64 t, %1; cvt.u32.u64 %0, t; }" : "=r"(a) : "l"(p));
    return a;
}
__device__ __forceinline__ void mma_f16(
    float c[4], uint32_t a0, uint32_t a1, uint32_t a2, uint32_t a3,
    uint32_t b0, uint32_t b1)
{
    asm volatile(
        "mma.sync.aligned.m16n8k16.row.col.f32.f16.f16.f32 "
        "{%0,%1,%2,%3}, {%4,%5,%6,%7}, {%8,%9}, {%0,%1,%2,%3};"
        : "+f"(c[0]), "+f"(c[1]), "+f"(c[2]), "+f"(c[3])
        : "r"(a0), "r"(a1), "r"(a2), "r"(a3), "r"(b0), "r"(b1));
}
__device__ __forceinline__ void ldsm_x4(
    uint32_t& r0, uint32_t& r1, uint32_t& r2, uint32_t& r3, uint32_t addr)
{
    asm volatile("ldmatrix.sync.aligned.m8n8.x4.shared.b16 {%0,%1,%2,%3}, [%4];"
                 : "=r"(r0), "=r"(r1), "=r"(r2), "=r"(r3) : "r"(addr));
}
__device__ __forceinline__ void ldsm_x4_t(
    uint32_t& r0, uint32_t& r1, uint32_t& r2, uint32_t& r3, uint32_t addr)
{
    asm volatile("ldmatrix.sync.aligned.m8n8.x4.trans.shared.b16 {%0,%1,%2,%3}, [%4];"
                 : "=r"(r0), "=r"(r1), "=r"(r2), "=r"(r3) : "r"(addr));
}
__device__ __forceinline__ void cp16(uint32_t dst, const void* src) {
    asm volatile("cp.async.cg.shared.global [%0], [%1], 16;" :: "r"(dst), "l"(src));
}
#define CP_COMMIT() asm volatile("cp.async.commit_group;" ::: "memory")
#define CP_WAIT1()  asm volatile("cp.async.wait_group 1;" ::: "memory")

// B_NK = true : C[m][n] = sum_k A[m][k] * B[n][k]   (B [N,K] half)
// B_NK = false: C[m][n] = sum_k A[m][k] * B[k][n]   (B [K,N] half)
template <bool B_NK, typename OutT>
__device__ __forceinline__ void gemm_body(
    const __half* __restrict__ A, long lda,
    const __half* __restrict__ B, long ldb,
    OutT* __restrict__ C, long ldc, int K)
{
    extern __shared__ char dynsm[];
    const uint32_t sraw = smem_u32(dynsm);
    const uint32_t sb   = (sraw + 127) & ~127u;

    const int t = threadIdx.x, lane = t & 31, warp = t >> 5;
    const int m0 = blockIdx.y * BM, n0 = blockIdx.x * BN;
    const int wm = (warp >> 2) * 64, wn = (warp & 3) * 64;
    const int fr = lane >> 2, fc = lane & 3;

    auto load_stage = [&](int slot, int k0) {
        const uint32_t ab = sb + slot * STAGE;
        const uint32_t bb = ab + A_STAGE;
        // A: 128 rows x 8 chunks
#pragma unroll
        for (int it = 0; it < 4; it++) {
            int idx = t + it * 256;
            int row = idx >> 3, c = idx & 7;
            cp16(ab + row * 128 + ((c ^ (row & 7)) << 4),
                 A + (long)(m0 + row) * lda + k0 + c * 8);
        }
        if (B_NK) {
            // B: 256 rows x 8 chunks
#pragma unroll
            for (int it = 0; it < 8; it++) {
                int idx = t + it * 256;
                int row = idx >> 3, c = idx & 7;
                cp16(bb + row * 128 + ((c ^ (row & 7)) << 4),
                     B + (long)(n0 + row) * ldb + k0 + c * 8);
            }
        } else {
            // V: 64 k-rows x 32 chunks (512B rows)
#pragma unroll
            for (int it = 0; it < 8; it++) {
                int idx = t + it * 256;
                int k = idx >> 5, c = idx & 31;
                cp16(bb + k * 512 + ((c ^ (k & 7)) << 4),
                     B + (long)(k0 + k) * ldb + n0 + c * 8);
            }
        }
    };

    float acc[4][8][4];
#pragma unroll
    for (int i = 0; i < 4; i++)
#pragma unroll
        for (int j = 0; j < 8; j++)
#pragma unroll
            for (int r = 0; r < 4; r++) acc[i][j][r] = 0.f;

    const int x7    = lane & 7;
    const int a_row = wm + ((lane >> 3) & 1) * 8 + x7;
    const int a_kc  = (lane >> 4) & 1;
    const int b_row = wn + ((lane >> 4) & 1) * 8 + x7;   // B_NK
    const int b_kc  = (lane >> 3) & 1;
    const int v_krow = ((lane >> 3) & 1) * 8 + x7;       // B_KN
    const int v_cof  = (lane >> 4) & 1;

    const int nT = K / TBK;
    load_stage(0, 0);   CP_COMMIT();
    load_stage(1, TBK); CP_COMMIT();

    for (int ti = 0; ti < nT; ti++) {
        CP_WAIT1();
        __syncthreads();

        const int pf = ti + 2;
        if (pf < nT) load_stage(pf % STAGES, pf * TBK);
        CP_COMMIT();

        const int slot = ti % STAGES;
        const uint32_t ab = sb + slot * STAGE;
        const uint32_t bb = ab + A_STAGE;

#pragma unroll
        for (int ks = 0; ks < 4; ks++) {      // 4 x K=16
            uint32_t af[4][4], bf[8][2];
#pragma unroll
            for (int im = 0; im < 4; im++) {
                uint32_t addr = ab + (a_row + im * 16) * 128 +
                                (((ks * 2 + a_kc) ^ x7) << 4);
                ldsm_x4(af[im][0], af[im][1], af[im][2], af[im][3], addr);
            }
            if (B_NK) {
#pragma unroll
                for (int p = 0; p < 4; p++) {
                    uint32_t addr = bb + (b_row + p * 16) * 128 +
                                    (((ks * 2 + b_kc) ^ x7) << 4);
                    ldsm_x4(bf[2 * p][0], bf[2 * p][1],
                            bf[2 * p + 1][0], bf[2 * p + 1][1], addr);
                }
            } else {
#pragma unroll
                for (int p = 0; p < 4; p++) {
                    int row_k = ks * 16 + v_krow;
                    int chunk = (wn >> 3) + 2 * p + v_cof;
                    uint32_t addr = bb + row_k * 512 + ((chunk ^ x7) << 4);
                    ldsm_x4_t(bf[2 * p][0], bf[2 * p][1],
                              bf[2 * p + 1][0], bf[2 * p + 1][1], addr);
                }
            }
#pragma unroll
            for (int im = 0; im < 4; im++)
#pragma unroll
                for (int in = 0; in < 8; in++)
                    mma_f16(acc[im][in], af[im][0], af[im][1], af[im][2], af[im][3],
                            bf[in][0], bf[in][1]);
        }
    }

#pragma unroll
    for (int im = 0; im < 4; im++) {
#pragma unroll
        for (int in = 0; in < 8; in++) {
            long row = m0 + wm + im * 16 + fr;
            long col = n0 + wn + in * 8 + 2 * fc;
            if (sizeof(OutT) == 2) {
                __half2* p0 = (__half2*)((__half*)C + row * ldc + col);
                __half2* p1 = (__half2*)((__half*)C + (row + 8) * ldc + col);
                *p0 = __floats2half2_rn(acc[im][in][0], acc[im][in][1]);
                *p1 = __floats2half2_rn(acc[im][in][2], acc[im][in][3]);
            } else {
                *(float2*)((float*)C + row * ldc + col) =
                    make_float2(acc[im][in][0], acc[im][in][1]);
                *(float2*)((float*)C + (row + 8) * ldc + col) =
                    make_float2(acc[im][in][2], acc[im][in][3]);
            }
        }
    }
}

// ---------------------------------------------------------------------------
__global__ __launch_bounds__(256) void round_all_kernel(
    const float* __restrict__ x,  const float* __restrict__ Wq,
    const float* __restrict__ Wk, const float* __restrict__ Wv)
{
    const long i = ((long)blockIdx.x * 256 + threadIdx.x) * 8;
    const long NX = (long)MTOT * DM;
    const long NW = (long)DM * DM;
    const float* src; __half* dst; long off;
    if (i < NX)               { src = x;  dst = g_X;          off = i; }
    else if (i < NX + NW)     { src = Wq; dst = g_W;          off = i - NX; }
    else if (i < NX + 2 * NW) { src = Wk; dst = g_W + NW;     off = i - NX - NW; }
    else                      { src = Wv; dst = g_W + 2 * NW; off = i - NX - 2 * NW; }
    float4 v0 = *(const float4*)(src + off);
    float4 v1 = *(const float4*)(src + off + 4);
    __half2 h0 = __floats2half2_rn(v0.x, v0.y);
    __half2 h1 = __floats2half2_rn(v0.z, v0.w);
    __half2 h2 = __floats2half2_rn(v1.x, v1.y);
    __half2 h3 = __floats2half2_rn(v1.z, v1.w);
    uint4 u;
    u.x = *(uint32_t*)&h0; u.y = *(uint32_t*)&h1;
    u.z = *(uint32_t*)&h2; u.w = *(uint32_t*)&h3;
    *(uint4*)(dst + off) = u;
}

__global__ __launch_bounds__(256) void qkv_kernel()
{
    const __half* W = g_W + (long)blockIdx.z * DM * DM;
    __half* C = (blockIdx.z == 0) ? g_Q : (blockIdx.z == 1) ? g_K : g_V;
    gemm_body<true, __half>(g_X, DM, W, DM, C, DM, DM);
}

__global__ __launch_bounds__(256) void scores_kernel()
{
    const long b = blockIdx.z;
    gemm_body<true, float>(g_Q + b * (long)SEQ * DM, DM,
                           g_K + b * (long)SEQ * DM, DM,
                           g_P + b * (long)SEQ * SEQ, SEQ, DM);
}

__global__ __launch_bounds__(256) void out_kernel(float* __restrict__ out)
{
    const long b = blockIdx.z;
    gemm_body<false, float>(g_Ph + b * (long)SEQ * SEQ, SEQ,
                            g_V + b * (long)SEQ * DM, DM,
                            out + b * (long)SEQ * DM, DM, SEQ);
}

__global__ __launch_bounds__(256) void softmax_kernel()
{
    const long row = blockIdx.x;
    const float* p = g_P + row * (long)SEQ;
    __half* q = g_Ph + row * (long)SEQ;
    const int t = threadIdx.x;
    const float scale = 0.03125f;  // 1/sqrt(1024)

    float4 v0 = ((const float4*)p)[t];
    float4 v1 = ((const float4*)p)[t + 256];

    float m = fmaxf(fmaxf(fmaxf(v0.x, v0.y), fmaxf(v0.z, v0.w)),
                    fmaxf(fmaxf(v1.x, v1.y), fmaxf(v1.z, v1.w)));
    m *= scale;

    __shared__ float red[256];
    red[t] = m; __syncthreads();
#pragma unroll
    for (int s = 128; s > 0; s >>= 1) {
        if (t < s) red[t] = fmaxf(red[t], red[t + s]);
        __syncthreads();
    }
    const float rowmax = red[0];
    __syncthreads();

    float e[8];
    e[0] = __expf(fmaf(v0.x, scale, -rowmax));
    e[1] = __expf(fmaf(v0.y, scale, -rowmax));
    e[2] = __expf(fmaf(v0.z, scale, -rowmax));
    e[3] = __expf(fmaf(v0.w, scale, -rowmax));
    e[4] = __expf(fmaf(v1.x, scale, -rowmax));
    e[5] = __expf(fmaf(v1.y, scale, -rowmax));
    e[6] = __expf(fmaf(v1.z, scale, -rowmax));
    e[7] = __expf(fmaf(v1.w, scale, -rowmax));

    float s8 = e[0]+e[1]+e[2]+e[3]+e[4]+e[5]+e[6]+e[7];
    red[t] = s8; __syncthreads();
#pragma unroll
    for (int s = 128; s > 0; s >>= 1) {
        if (t < s) red[t] += red[t + s];
        __syncthreads();
    }
    const float inv = 1.0f / red[0];

    __half2 h0 = __floats2half2_rn(e[0]*inv, e[1]*inv);
    __half2 h1 = __floats2half2_rn(e[2]*inv, e[3]*inv);
    __half2 h2 = __floats2half2_rn(e[4]*inv, e[5]*inv);
    __half2 h3 = __floats2half2_rn(e[6]*inv, e[7]*inv);
    uint2 u0; u0.x = *(uint32_t*)&h0; u0.y = *(uint32_t*)&h1;
    uint2 u1; u1.x = *(uint32_t*)&h2; u1.y = *(uint32_t*)&h3;
    *(uint2*)(q + t * 4)         = u0;
    *(uint2*)(q + (t + 256) * 4) = u1;
}

// ---------------------------------------------------------------------------
extern "C" void kernel_launch(void* const* d_in, const int* in_sizes, int n_in,
                              void* d_out, int out_size)
{
    const float* x  = (const float*)d_in[0];
    const float* Wq = (const float*)d_in[1];
    const float* Wk = (const float*)d_in[2];
    const float* Wv = (const float*)d_in[3];
    float* out = (float*)d_out;

    static bool attr_done = false;
    if (!attr_done) {
        cudaFuncSetAttribute(qkv_kernel,    cudaFuncAttributeMaxDynamicSharedMemorySize, DYN_BYTES);
        cudaFuncSetAttribute(scores_kernel, cudaFuncAttributeMaxDynamicSharedMemorySize, DYN_BYTES);
        cudaFuncSetAttribute(out_kernel,    cudaFuncAttributeMaxDynamicSharedMemorySize, DYN_BYTES);
        attr_done = true;
    }

    dim3 blk(256);
    const long totalElems = (long)MTOT * DM + 3L * DM * DM;
    round_all_kernel<<<(unsigned)(totalElems / 2048), blk>>>(x, Wq, Wk, Wv);

    qkv_kernel   <<<dim3(DM / BN,  MTOT / BM, 3),     blk, DYN_BYTES>>>();
    scores_kernel<<<dim3(SEQ / BN, SEQ / BM,  BATCH), blk, DYN_BYTES>>>();
    softmax_kernel<<<MTOT, 256>>>();
    out_kernel   <<<dim3(DM / BN,  SEQ / BM,  BATCH), blk, DYN_BYTES>>>(out);
}

// round 11
// speedup vs baseline: 1.1739x; 1.1739x over previous
#include <cuda_runtime.h>
#include <cuda_fp16.h>
#include <cstdint>

// Shape: x [B=4, S=2048, D=1024] fp32; Wq/Wk/Wv [D, D] fp32 (y = x @ W^T)
#define BATCH 4
#define SEQ   2048
#define DM    1024
#define MTOT  (BATCH * SEQ)   // 8192

__device__ __half g_X[MTOT * DM];
__device__ __half g_W[3 * DM * DM];
__device__ __half g_Q[MTOT * DM];
__device__ __half g_K[MTOT * DM];
__device__ __half g_V[MTOT * DM];
__device__ float  g_P[(long)MTOT * SEQ];    // fp32 scores
__device__ __half g_Ph[(long)MTOT * SEQ];   // fp16 probs

// ---------------------------------------------------------------------------
// FP16 mma.sync (m16n8k16) GEMM, cp.async 3-stage, BK=64 halves.
// Block tile 128x128, 4 warps (128 threads) in 2x2, warp tile 64x64.
// A/B_NK tiles: 128 rows x 128B, xor swizzle (chunk ^= row&7).
// B_KN tile (V): 64 k-rows x 256B (16 chunks), same swizzle, ldmatrix.trans.
// ---------------------------------------------------------------------------
#define BM 128
#define BN 128
#define TBK 64
#define NTHR 128
#define STAGES 3
#define A_STAGE 16384
#define B_STAGE 16384
#define STAGE   (A_STAGE + B_STAGE)
#define DYN_BYTES (STAGES * STAGE + 256)

__device__ __forceinline__ uint32_t smem_u32(const void* p) {
    uint32_t a;
    asm("{ .reg .u64 t; cvta.to.shared.u64 t, %1; cvt.u32.u64 %0, t; }" : "=r"(a) : "l"(p));
    return a;
}
__device__ __forceinline__ void mma_f16(
    float c[4], uint32_t a0, uint32_t a1, uint32_t a2, uint32_t a3,
    uint32_t b0, uint32_t b1)
{
    asm volatile(
        "mma.sync.aligned.m16n8k16.row.col.f32.f16.f16.f32 "
        "{%0,%1,%2,%3}, {%4,%5,%6,%7}, {%8,%9}, {%0,%1,%2,%3};"
        : "+f"(c[0]), "+f"(c[1]), "+f"(c[2]), "+f"(c[3])
        : "r"(a0), "r"(a1), "r"(a2), "r"(a3), "r"(b0), "r"(b1));
}
__device__ __forceinline__ void ldsm_x4(
    uint32_t& r0, uint32_t& r1, uint32_t& r2, uint32_t& r3, uint32_t addr)
{
    asm volatile("ldmatrix.sync.aligned.m8n8.x4.shared.b16 {%0,%1,%2,%3}, [%4];"
                 : "=r"(r0), "=r"(r1), "=r"(r2), "=r"(r3) : "r"(addr));
}
__device__ __forceinline__ void ldsm_x4_t(
    uint32_t& r0, uint32_t& r1, uint32_t& r2, uint32_t& r3, uint32_t addr)
{
    asm volatile("ldmatrix.sync.aligned.m8n8.x4.trans.shared.b16 {%0,%1,%2,%3}, [%4];"
                 : "=r"(r0), "=r"(r1), "=r"(r2), "=r"(r3) : "r"(addr));
}
__device__ __forceinline__ void cp16(uint32_t dst, const void* src) {
    asm volatile("cp.async.cg.shared.global [%0], [%1], 16;" :: "r"(dst), "l"(src));
}
#define CP_COMMIT() asm volatile("cp.async.commit_group;" ::: "memory")
#define CP_WAIT1()  asm volatile("cp.async.wait_group 1;" ::: "memory")

// B_NK = true : C[m][n] = sum_k A[m][k] * B[n][k]   (B [N,K] half)
// B_NK = false: C[m][n] = sum_k A[m][k] * B[k][n]   (B [K,N] half)
template <bool B_NK, typename OutT>
__device__ __forceinline__ void gemm_body(
    const __half* __restrict__ A, long lda,
    const __half* __restrict__ B, long ldb,
    OutT* __restrict__ C, long ldc, int K)
{
    extern __shared__ char dynsm[];
    const uint32_t sraw = smem_u32(dynsm);
    const uint32_t sb   = (sraw + 127) & ~127u;

    const int t = threadIdx.x, lane = t & 31, warp = t >> 5;
    const int m0 = blockIdx.y * BM, n0 = blockIdx.x * BN;
    const int wm = (warp >> 1) * 64, wn = (warp & 1) * 64;
    const int fr = lane >> 2, fc = lane & 3;

    auto load_stage = [&](int slot, int k0) {
        const uint32_t ab = sb + slot * STAGE;
        const uint32_t bb = ab + A_STAGE;
        // A: 128 rows x 8 chunks of 8 halves (1024 cp16, 8/thread)
#pragma unroll
        for (int it = 0; it < 8; it++) {
            int idx = t + it * NTHR;
            int row = idx >> 3, c = idx & 7;
            cp16(ab + row * 128 + ((c ^ (row & 7)) << 4),
                 A + (long)(m0 + row) * lda + k0 + c * 8);
        }
        if (B_NK) {
#pragma unroll
            for (int it = 0; it < 8; it++) {
                int idx = t + it * NTHR;
                int row = idx >> 3, c = idx & 7;
                cp16(bb + row * 128 + ((c ^ (row & 7)) << 4),
                     B + (long)(n0 + row) * ldb + k0 + c * 8);
            }
        } else {
            // V: 64 k-rows x 16 chunks (256B rows)
#pragma unroll
            for (int it = 0; it < 8; it++) {
                int idx = t + it * NTHR;
                int k = idx >> 4, c = idx & 15;
                cp16(bb + k * 256 + ((c ^ (k & 7)) << 4),
                     B + (long)(k0 + k) * ldb + n0 + c * 8);
            }
        }
    };

    float acc[4][8][4];
#pragma unroll
    for (int i = 0; i < 4; i++)
#pragma unroll
        for (int j = 0; j < 8; j++)
#pragma unroll
            for (int r = 0; r < 4; r++) acc[i][j][r] = 0.f;

    const int x7    = lane & 7;
    const int a_row = wm + ((lane >> 3) & 1) * 8 + x7;
    const int a_kc  = (lane >> 4) & 1;
    const int b_row = wn + ((lane >> 4) & 1) * 8 + x7;   // B_NK
    const int b_kc  = (lane >> 3) & 1;
    const int v_krow = ((lane >> 3) & 1) * 8 + x7;       // B_KN
    const int v_cof  = (lane >> 4) & 1;

    const int nT = K / TBK;
    load_stage(0, 0);   CP_COMMIT();
    load_stage(1, TBK); CP_COMMIT();

    for (int ti = 0; ti < nT; ti++) {
        CP_WAIT1();
        __syncthreads();

        const int pf = ti + 2;
        if (pf < nT) load_stage(pf % STAGES, pf * TBK);
        CP_COMMIT();

        const int slot = ti % STAGES;
        const uint32_t ab = sb + slot * STAGE;
        const uint32_t bb = ab + A_STAGE;

#pragma unroll
        for (int ks = 0; ks < 4; ks++) {      // 4 x K=16 per BK=64
            uint32_t af[4][4], bf[8][2];
#pragma unroll
            for (int im = 0; im < 4; im++) {
                uint32_t addr = ab + (a_row + im * 16) * 128 +
                                (((ks * 2 + a_kc) ^ x7) << 4);
                ldsm_x4(af[im][0], af[im][1], af[im][2], af[im][3], addr);
            }
            if (B_NK) {
#pragma unroll
                for (int p = 0; p < 4; p++) {
                    uint32_t addr = bb + (b_row + p * 16) * 128 +
                                    (((ks * 2 + b_kc) ^ x7) << 4);
                    ldsm_x4(bf[2 * p][0], bf[2 * p][1],
                            bf[2 * p + 1][0], bf[2 * p + 1][1], addr);
                }
            } else {
#pragma unroll
                for (int p = 0; p < 4; p++) {
                    int row_k = ks * 16 + v_krow;
                    int chunk = (wn >> 3) + 2 * p + v_cof;
                    uint32_t addr = bb + row_k * 256 + ((chunk ^ x7) << 4);
                    ldsm_x4_t(bf[2 * p][0], bf[2 * p][1],
                              bf[2 * p + 1][0], bf[2 * p + 1][1], addr);
                }
            }
#pragma unroll
            for (int im = 0; im < 4; im++)
#pragma unroll
                for (int in = 0; in < 8; in++)
                    mma_f16(acc[im][in], af[im][0], af[im][1], af[im][2], af[im][3],
                            bf[in][0], bf[in][1]);
        }
    }

#pragma unroll
    for (int im = 0; im < 4; im++) {
#pragma unroll
        for (int in = 0; in < 8; in++) {
            long row = m0 + wm + im * 16 + fr;
            long col = n0 + wn + in * 8 + 2 * fc;
            if (sizeof(OutT) == 2) {
                __half2* p0 = (__half2*)((__half*)C + row * ldc + col);
                __half2* p1 = (__half2*)((__half*)C + (row + 8) * ldc + col);
                *p0 = __floats2half2_rn(acc[im][in][0], acc[im][in][1]);
                *p1 = __floats2half2_rn(acc[im][in][2], acc[im][in][3]);
            } else {
                *(float2*)((float*)C + row * ldc + col) =
                    make_float2(acc[im][in][0], acc[im][in][1]);
                *(float2*)((float*)C + (row + 8) * ldc + col) =
                    make_float2(acc[im][in][2], acc[im][in][3]);
            }
        }
    }
}

// ---------------------------------------------------------------------------
__global__ __launch_bounds__(256) void round_all_kernel(
    const float* __restrict__ x,  const float* __restrict__ Wq,
    const float* __restrict__ Wk, const float* __restrict__ Wv)
{
    const long i = ((long)blockIdx.x * 256 + threadIdx.x) * 8;
    const long NX = (long)MTOT * DM;
    const long NW = (long)DM * DM;
    const float* src; __half* dst; long off;
    if (i < NX)               { src = x;  dst = g_X;          off = i; }
    else if (i < NX + NW)     { src = Wq; dst = g_W;          off = i - NX; }
    else if (i < NX + 2 * NW) { src = Wk; dst = g_W + NW;     off = i - NX - NW; }
    else                      { src = Wv; dst = g_W + 2 * NW; off = i - NX - 2 * NW; }
    float4 v0 = *(const float4*)(src + off);
    float4 v1 = *(const float4*)(src + off + 4);
    __half2 h0 = __floats2half2_rn(v0.x, v0.y);
    __half2 h1 = __floats2half2_rn(v0.z, v0.w);
    __half2 h2 = __floats2half2_rn(v1.x, v1.y);
    __half2 h3 = __floats2half2_rn(v1.z, v1.w);
    uint4 u;
    u.x = *(uint32_t*)&h0; u.y = *(uint32_t*)&h1;
    u.z = *(uint32_t*)&h2; u.w = *(uint32_t*)&h3;
    *(uint4*)(dst + off) = u;
}

__global__ __launch_bounds__(NTHR, 2) void qkv_kernel()
{
    const __half* W = g_W + (long)blockIdx.z * DM * DM;
    __half* C = (blockIdx.z == 0) ? g_Q : (blockIdx.z == 1) ? g_K : g_V;
    gemm_body<true, __half>(g_X, DM, W, DM, C, DM, DM);
}

__global__ __launch_bounds__(NTHR, 2) void scores_kernel()
{
    const long b = blockIdx.z;
    gemm_body<true, float>(g_Q + b * (long)SEQ * DM, DM,
                           g_K + b * (long)SEQ * DM, DM,
                           g_P + b * (long)SEQ * SEQ, SEQ, DM);
}

__global__ __launch_bounds__(NTHR, 2) void out_kernel(float* __restrict__ out)
{
    const long b = blockIdx.z;
    gemm_body<false, float>(g_Ph + b * (long)SEQ * SEQ, SEQ,
                            g_V + b * (long)SEQ * DM, DM,
                            out + b * (long)SEQ * DM, DM, SEQ);
}

__global__ __launch_bounds__(256) void softmax_kernel()
{
    const long row = blockIdx.x;
    const float* p = g_P + row * (long)SEQ;
    __half* q = g_Ph + row * (long)SEQ;
    const int t = threadIdx.x;
    const float scale = 0.03125f;  // 1/sqrt(1024)

    float4 v0 = ((const float4*)p)[t];
    float4 v1 = ((const float4*)p)[t + 256];

    float m = fmaxf(fmaxf(fmaxf(v0.x, v0.y), fmaxf(v0.z, v0.w)),
                    fmaxf(fmaxf(v1.x, v1.y), fmaxf(v1.z, v1.w)));
    m *= scale;

    __shared__ float red[256];
    red[t] = m; __syncthreads();
#pragma unroll
    for (int s = 128; s > 0; s >>= 1) {
        if (t < s) red[t] = fmaxf(red[t], red[t + s]);
        __syncthreads();
    }
    const float rowmax = red[0];
    __syncthreads();

    float e[8];
    e[0] = __expf(fmaf(v0.x, scale, -rowmax));
    e[1] = __expf(fmaf(v0.y, scale, -rowmax));
    e[2] = __expf(fmaf(v0.z, scale, -rowmax));
    e[3] = __expf(fmaf(v0.w, scale, -rowmax));
    e[4] = __expf(fmaf(v1.x, scale, -rowmax));
    e[5] = __expf(fmaf(v1.y, scale, -rowmax));
    e[6] = __expf(fmaf(v1.z, scale, -rowmax));
    e[7] = __expf(fmaf(v1.w, scale, -rowmax));

    float s8 = e[0]+e[1]+e[2]+e[3]+e[4]+e[5]+e[6]+e[7];
    red[t] = s8; __syncthreads();
#pragma unroll
    for (int s = 128; s > 0; s >>= 1) {
        if (t < s) red[t] += red[t + s];
        __syncthreads();
    }
    const float inv = 1.0f / red[0];

    __half2 h0 = __floats2half2_rn(e[0]*inv, e[1]*inv);
    __half2 h1 = __floats2half2_rn(e[2]*inv, e[3]*inv);
    __half2 h2 = __floats2half2_rn(e[4]*inv, e[5]*inv);
    __half2 h3 = __floats2half2_rn(e[6]*inv, e[7]*inv);
    uint2 u0; u0.x = *(uint32_t*)&h0; u0.y = *(uint32_t*)&h1;
    uint2 u1; u1.x = *(uint32_t*)&h2; u1.y = *(uint32_t*)&h3;
    *(uint2*)(q + t * 4)         = u0;
    *(uint2*)(q + (t + 256) * 4) = u1;
}

// ---------------------------------------------------------------------------
extern "C" void kernel_launch(void* const* d_in, const int* in_sizes, int n_in,
                              void* d_out, int out_size)
{
    const float* x  = (const float*)d_in[0];
    const float* Wq = (const float*)d_in[1];
    const float* Wk = (const float*)d_in[2];
    const float* Wv = (const float*)d_in[3];
    float* out = (float*)d_out;

    static bool attr_done = false;
    if (!attr_done) {
        cudaFuncSetAttribute(qkv_kernel,    cudaFuncAttributeMaxDynamicSharedMemorySize, DYN_BYTES);
        cudaFuncSetAttribute(scores_kernel, cudaFuncAttributeMaxDynamicSharedMemorySize, DYN_BYTES);
        cudaFuncSetAttribute(out_kernel,    cudaFuncAttributeMaxDynamicSharedMemorySize, DYN_BYTES);
        attr_done = true;
    }

    dim3 blk(NTHR);
    const long totalElems = (long)MTOT * DM + 3L * DM * DM;
    round_all_kernel<<<(unsigned)(totalElems / 2048), 256>>>(x, Wq, Wk, Wv);

    qkv_kernel   <<<dim3(DM / BN,  MTOT / BM, 3),     blk, DYN_BYTES>>>();
    scores_kernel<<<dim3(SEQ / BN, SEQ / BM,  BATCH), blk, DYN_BYTES>>>();
    softmax_kernel<<<MTOT, 256>>>();
    out_kernel   <<<dim3(DM / BN,  SEQ / BM,  BATCH), blk, DYN_BYTES>>>(out);
}

// round 12
// speedup vs baseline: 1.2168x; 1.0365x over previous
#include <cuda_runtime.h>
#include <cuda_fp16.h>
#include <cstdint>

// Shape: x [B=4, S=2048, D=1024] fp32; Wq/Wk/Wv [D, D] fp32 (y = x @ W.T)
#define BATCH 4
#define SEQ   2048
#define DM    1024
#define MTOT  (BATCH * SEQ)   // 8192

__device__ __half g_X[MTOT * DM];
__device__ __half g_W[3 * DM * DM];
__device__ __half g_Q[MTOT * DM];
__device__ __half g_K[MTOT * DM];
__device__ __half g_V[MTOT * DM];
__device__ __half g_Ph[(long)MTOT * SEQ];   // fp16 unnormalized exp(scores/32)

// ---------------------------------------------------------------------------
// FP16 mma.sync (m16n8k16) GEMM, cp.async 3-stage, BK=64 halves.
// Block tile 128x128, 4 warps (128 threads) 2x2, warp tile 64x64.
// EPI: 0 = plain half stores (qkv)
//      1 = exp(scale*acc) half stores (scores; softmax fused, no max shift)
//      2 = float stores divided by row-sum computed via ones-MMA (out)
// ---------------------------------------------------------------------------
#define BM 128
#define BN 128
#define TBK 64
#define NTHR 128
#define STAGES 3
#define A_STAGE 16384
#define B_STAGE 16384
#define STAGE   (A_STAGE + B_STAGE)
#define DYN_BYTES (STAGES * STAGE + 256)
#define ONES_H2 0x3C003C00u   // half2(1.0, 1.0)

__device__ __forceinline__ uint32_t smem_u32(const void* p) {
    uint32_t a;
    asm("{ .reg .u64 t; cvta.to.shared.u64 t, %1; cvt.u32.u64 %0, t; }" : "=r"(a) : "l"(p));
    return a;
}
__device__ __forceinline__ void mma_f16(
    float c[4], uint32_t a0, uint32_t a1, uint32_t a2, uint32_t a3,
    uint32_t b0, uint32_t b1)
{
    asm volatile(
        "mma.sync.aligned.m16n8k16.row.col.f32.f16.f16.f32 "
        "{%0,%1,%2,%3}, {%4,%5,%6,%7}, {%8,%9}, {%0,%1,%2,%3};"
        : "+f"(c[0]), "+f"(c[1]), "+f"(c[2]), "+f"(c[3])
        : "r"(a0), "r"(a1), "r"(a2), "r"(a3), "r"(b0), "r"(b1));
}
__device__ __forceinline__ void ldsm_x4(
    uint32_t& r0, uint32_t& r1, uint32_t& r2, uint32_t& r3, uint32_t addr)
{
    asm volatile("ldmatrix.sync.aligned.m8n8.x4.shared.b16 {%0,%1,%2,%3}, [%4];"
                 : "=r"(r0), "=r"(r1), "=r"(r2), "=r"(r3) : "r"(addr));
}
__device__ __forceinline__ void ldsm_x4_t(
    uint32_t& r0, uint32_t& r1, uint32_t& r2, uint32_t& r3, uint32_t addr)
{
    asm volatile("ldmatrix.sync.aligned.m8n8.x4.trans.shared.b16 {%0,%1,%2,%3}, [%4];"
                 : "=r"(r0), "=r"(r1), "=r"(r2), "=r"(r3) : "r"(addr));
}
__device__ __forceinline__ void cp16(uint32_t dst, const void* src) {
    asm volatile("cp.async.cg.shared.global [%0], [%1], 16;" :: "r"(dst), "l"(src));
}
#define CP_COMMIT() asm volatile("cp.async.commit_group;" ::: "memory")
#define CP_WAIT1()  asm volatile("cp.async.wait_group 1;" ::: "memory")

// B_NK = true : C[m][n] = sum_k A[m][k] * B[n][k]   (B [N,K] half)
// B_NK = false: C[m][n] = sum_k A[m][k] * B[k][n]   (B [K,N] half)
template <bool B_NK, int EPI, typename OutT>
__device__ __forceinline__ void gemm_body(
    const __half* __restrict__ A, long lda,
    const __half* __restrict__ B, long ldb,
    OutT* __restrict__ C, long ldc, int K)
{
    extern __shared__ char dynsm[];
    const uint32_t sraw = smem_u32(dynsm);
    const uint32_t sb   = (sraw + 127) & ~127u;

    const int t = threadIdx.x, lane = t & 31, warp = t >> 5;
    const int m0 = blockIdx.y * BM, n0 = blockIdx.x * BN;
    const int wm = (warp >> 1) * 64, wn = (warp & 1) * 64;
    const int fr = lane >> 2, fc = lane & 3;

    auto load_stage = [&](int slot, int k0) {
        const uint32_t ab = sb + slot * STAGE;
        const uint32_t bb = ab + A_STAGE;
#pragma unroll
        for (int it = 0; it < 8; it++) {
            int idx = t + it * NTHR;
            int row = idx >> 3, c = idx & 7;
            cp16(ab + row * 128 + ((c ^ (row & 7)) << 4),
                 A + (long)(m0 + row) * lda + k0 + c * 8);
        }
        if (B_NK) {
#pragma unroll
            for (int it = 0; it < 8; it++) {
                int idx = t + it * NTHR;
                int row = idx >> 3, c = idx & 7;
                cp16(bb + row * 128 + ((c ^ (row & 7)) << 4),
                     B + (long)(n0 + row) * ldb + k0 + c * 8);
            }
        } else {
#pragma unroll
            for (int it = 0; it < 8; it++) {
                int idx = t + it * NTHR;
                int k = idx >> 4, c = idx & 15;
                cp16(bb + k * 256 + ((c ^ (k & 7)) << 4),
                     B + (long)(k0 + k) * ldb + n0 + c * 8);
            }
        }
    };

    float acc[4][8][4];
#pragma unroll
    for (int i = 0; i < 4; i++)
#pragma unroll
        for (int j = 0; j < 8; j++)
#pragma unroll
            for (int r = 0; r < 4; r++) acc[i][j][r] = 0.f;

    float accS[4][4];   // row sums via ones-MMA (EPI==2 only)
    if (EPI == 2) {
#pragma unroll
        for (int i = 0; i < 4; i++)
#pragma unroll
            for (int r = 0; r < 4; r++) accS[i][r] = 0.f;
    }

    const int x7    = lane & 7;
    const int a_row = wm + ((lane >> 3) & 1) * 8 + x7;
    const int a_kc  = (lane >> 4) & 1;
    const int b_row = wn + ((lane >> 4) & 1) * 8 + x7;   // B_NK
    const int b_kc  = (lane >> 3) & 1;
    const int v_krow = ((lane >> 3) & 1) * 8 + x7;       // B_KN
    const int v_cof  = (lane >> 4) & 1;

    const int nT = K / TBK;
    load_stage(0, 0);   CP_COMMIT();
    load_stage(1, TBK); CP_COMMIT();

    for (int ti = 0; ti < nT; ti++) {
        CP_WAIT1();
        __syncthreads();

        const int pf = ti + 2;
        if (pf < nT) load_stage(pf % STAGES, pf * TBK);
        CP_COMMIT();

        const int slot = ti % STAGES;
        const uint32_t ab = sb + slot * STAGE;
        const uint32_t bb = ab + A_STAGE;

#pragma unroll
        for (int ks = 0; ks < 4; ks++) {      // 4 x K=16 per BK=64
            uint32_t af[4][4], bf[8][2];
#pragma unroll
            for (int im = 0; im < 4; im++) {
                uint32_t addr = ab + (a_row + im * 16) * 128 +
                                (((ks * 2 + a_kc) ^ x7) << 4);
                ldsm_x4(af[im][0], af[im][1], af[im][2], af[im][3], addr);
            }
            if (B_NK) {
#pragma unroll
                for (int p = 0; p < 4; p++) {
                    uint32_t addr = bb + (b_row + p * 16) * 128 +
                                    (((ks * 2 + b_kc) ^ x7) << 4);
                    ldsm_x4(bf[2 * p][0], bf[2 * p][1],
                            bf[2 * p + 1][0], bf[2 * p + 1][1], addr);
                }
            } else {
#pragma unroll
                for (int p = 0; p < 4; p++) {
                    int row_k = ks * 16 + v_krow;
                    int chunk = (wn >> 3) + 2 * p + v_cof;
                    uint32_t addr = bb + row_k * 256 + ((chunk ^ x7) << 4);
                    ldsm_x4_t(bf[2 * p][0], bf[2 * p][1],
                              bf[2 * p + 1][0], bf[2 * p + 1][1], addr);
                }
            }
#pragma unroll
            for (int im = 0; im < 4; im++)
#pragma unroll
                for (int in = 0; in < 8; in++)
                    mma_f16(acc[im][in], af[im][0], af[im][1], af[im][2], af[im][3],
                            bf[in][0], bf[in][1]);
            if (EPI == 2) {
#pragma unroll
                for (int im = 0; im < 4; im++)
                    mma_f16(accS[im], af[im][0], af[im][1], af[im][2], af[im][3],
                            ONES_H2, ONES_H2);
            }
        }
    }

    const float S = 0.03125f;   // 1/sqrt(1024)
#pragma unroll
    for (int im = 0; im < 4; im++) {
        float i0 = 1.f, i1 = 1.f;
        if (EPI == 2) { i0 = 1.0f / accS[im][0]; i1 = 1.0f / accS[im][2]; }
#pragma unroll
        for (int in = 0; in < 8; in++) {
            long row = m0 + wm + im * 16 + fr;
            long col = n0 + wn + in * 8 + 2 * fc;
            if (EPI == 0) {
                *(__half2*)((__half*)C + row * ldc + col) =
                    __floats2half2_rn(acc[im][in][0], acc[im][in][1]);
                *(__half2*)((__half*)C + (row + 8) * ldc + col) =
                    __floats2half2_rn(acc[im][in][2], acc[im][in][3]);
            } else if (EPI == 1) {
                *(__half2*)((__half*)C + row * ldc + col) =
                    __floats2half2_rn(__expf(acc[im][in][0] * S),
                                      __expf(acc[im][in][1] * S));
                *(__half2*)((__half*)C + (row + 8) * ldc + col) =
                    __floats2half2_rn(__expf(acc[im][in][2] * S),
                                      __expf(acc[im][in][3] * S));
            } else {
                *(float2*)((float*)C + row * ldc + col) =
                    make_float2(acc[im][in][0] * i0, acc[im][in][1] * i0);
                *(float2*)((float*)C + (row + 8) * ldc + col) =
                    make_float2(acc[im][in][2] * i1, acc[im][in][3] * i1);
            }
        }
    }
}

// ---------------------------------------------------------------------------
__global__ __launch_bounds__(256) void round_all_kernel(
    const float* __restrict__ x,  const float* __restrict__ Wq,
    const float* __restrict__ Wk, const float* __restrict__ Wv)
{
    const long i = ((long)blockIdx.x * 256 + threadIdx.x) * 8;
    const long NX = (long)MTOT * DM;
    const long NW = (long)DM * DM;
    const float* src; __half* dst; long off;
    if (i < NX)               { src = x;  dst = g_X;          off = i; }
    else if (i < NX + NW)     { src = Wq; dst = g_W;          off = i - NX; }
    else if (i < NX + 2 * NW) { src = Wk; dst = g_W + NW;     off = i - NX - NW; }
    else                      { src = Wv; dst = g_W + 2 * NW; off = i - NX - 2 * NW; }
    float4 v0 = *(const float4*)(src + off);
    float4 v1 = *(const float4*)(src + off + 4);
    __half2 h0 = __floats2half2_rn(v0.x, v0.y);
    __half2 h1 = __floats2half2_rn(v0.z, v0.w);
    __half2 h2 = __floats2half2_rn(v1.x, v1.y);
    __half2 h3 = __floats2half2_rn(v1.z, v1.w);
    uint4 u;
    u.x = *(uint32_t*)&h0; u.y = *(uint32_t*)&h1;
    u.z = *(uint32_t*)&h2; u.w = *(uint32_t*)&h3;
    *(uint4*)(dst + off) = u;
}

__global__ __launch_bounds__(NTHR, 2) void qkv_kernel()
{
    const __half* W = g_W + (long)blockIdx.z * DM * DM;
    __half* C = (blockIdx.z == 0) ? g_Q : (blockIdx.z == 1) ? g_K : g_V;
    gemm_body<true, 0, __half>(g_X, DM, W, DM, C, DM, DM);
}

// scores + fused softmax numerator: writes exp(QK^T/32) in fp16.
__global__ __launch_bounds__(NTHR, 2) void scores_kernel()
{
    const long b = blockIdx.z;
    gemm_body<true, 1, __half>(g_Q + b * (long)SEQ * DM, DM,
                               g_K + b * (long)SEQ * DM, DM,
                               g_Ph + b * (long)SEQ * SEQ, SEQ, DM);
}

// out = (e @ V) / rowsum(e); rowsum via ones-MMA in the mainloop.
__global__ __launch_bounds__(NTHR, 2) void out_kernel(float* __restrict__ out)
{
    const long b = blockIdx.z;
    gemm_body<false, 2, float>(g_Ph + b * (long)SEQ * SEQ, SEQ,
                               g_V + b * (long)SEQ * DM, DM,
                               out + b * (long)SEQ * DM, DM, SEQ);
}

// ---------------------------------------------------------------------------
extern "C" void kernel_launch(void* const* d_in, const int* in_sizes, int n_in,
                              void* d_out, int out_size)
{
    const float* x  = (const float*)d_in[0];
    const float* Wq = (const float*)d_in[1];
    const float* Wk = (const float*)d_in[2];
    const float* Wv = (const float*)d_in[3];
    float* out = (float*)d_out;

    static bool attr_done = false;
    if (!attr_done) {
        cudaFuncSetAttribute(qkv_kernel,    cudaFuncAttributeMaxDynamicSharedMemorySize, DYN_BYTES);
        cudaFuncSetAttribute(scores_kernel, cudaFuncAttributeMaxDynamicSharedMemorySize, DYN_BYTES);
        cudaFuncSetAttribute(out_kernel,    cudaFuncAttributeMaxDynamicSharedMemorySize, DYN_BYTES);
        attr_done = true;
    }

    dim3 blk(NTHR);
    const long totalElems = (long)MTOT * DM + 3L * DM * DM;
    round_all_kernel<<<(unsigned)(totalElems / 2048), 256>>>(x, Wq, Wk, Wv);

    qkv_kernel   <<<dim3(DM / BN,  MTOT / BM, 3),     blk, DYN_BYTES>>>();
    scores_kernel<<<dim3(SEQ / BN, SEQ / BM,  BATCH), blk, DYN_BYTES>>>();
    out_kernel   <<<dim3(DM / BN,  SEQ / BM,  BATCH), blk, DYN_BYTES>>>(out);
}

// round 13
// speedup vs baseline: 1.2169x; 1.0001x over previous
#include <cuda_runtime.h>
#include <cuda_fp16.h>
#include <cstdint>

// Shape: x [B=4, S=2048, D=1024] fp32; Wq/Wk/Wv [D, D] fp32 (y = x @ W.T)
#define BATCH 4
#define SEQ   2048
#define DM    1024
#define MTOT  (BATCH * SEQ)   // 8192

__device__ __half g_X[MTOT * DM];
__device__ __half g_W[3 * DM * DM];
__device__ __half g_Q[MTOT * DM];
__device__ __half g_K[MTOT * DM];
__device__ __half g_V[MTOT * DM];
__device__ __half g_Ph[(long)MTOT * SEQ];   // fp16 unnormalized exp(scores/32)

// ---------------------------------------------------------------------------
// FP16 mma.sync (m16n8k16) GEMM, cp.async 3-stage, BK=64 halves.
// Block tile 128x128, 4 warps (128 threads) 2x2, warp tile 64x64.
// EPI: 0 = plain half stores (qkv)
//      1 = exp(scale*acc) half stores (scores; softmax fused, no max shift)
//      2 = float stores divided by row-sum computed via ones-MMA (out)
// ---------------------------------------------------------------------------
#define BM 128
#define BN 128
#define TBK 64
#define NTHR 128
#define STAGES 3
#define A_STAGE 16384
#define B_STAGE 16384
#define STAGE   (A_STAGE + B_STAGE)
#define DYN_BYTES (STAGES * STAGE + 256)
#define ONES_H2 0x3C003C00u   // half2(1.0, 1.0)

__device__ __forceinline__ uint32_t smem_u32(const void* p) {
    uint32_t a;
    asm("{ .reg .u64 t; cvta.to.shared.u64 t, %1; cvt.u32.u64 %0, t; }" : "=r"(a) : "l"(p));
    return a;
}
__device__ __forceinline__ void mma_f16(
    float c[4], uint32_t a0, uint32_t a1, uint32_t a2, uint32_t a3,
    uint32_t b0, uint32_t b1)
{
    asm volatile(
        "mma.sync.aligned.m16n8k16.row.col.f32.f16.f16.f32 "
        "{%0,%1,%2,%3}, {%4,%5,%6,%7}, {%8,%9}, {%0,%1,%2,%3};"
        : "+f"(c[0]), "+f"(c[1]), "+f"(c[2]), "+f"(c[3])
        : "r"(a0), "r"(a1), "r"(a2), "r"(a3), "r"(b0), "r"(b1));
}
__device__ __forceinline__ void ldsm_x4(
    uint32_t& r0, uint32_t& r1, uint32_t& r2, uint32_t& r3, uint32_t addr)
{
    asm volatile("ldmatrix.sync.aligned.m8n8.x4.shared.b16 {%0,%1,%2,%3}, [%4];"
                 : "=r"(r0), "=r"(r1), "=r"(r2), "=r"(r3) : "r"(addr));
}
__device__ __forceinline__ void ldsm_x4_t(
    uint32_t& r0, uint32_t& r1, uint32_t& r2, uint32_t& r3, uint32_t addr)
{
    asm volatile("ldmatrix.sync.aligned.m8n8.x4.trans.shared.b16 {%0,%1,%2,%3}, [%4];"
                 : "=r"(r0), "=r"(r1), "=r"(r2), "=r"(r3) : "r"(addr));
}
__device__ __forceinline__ void cp16(uint32_t dst, const void* src) {
    asm volatile("cp.async.cg.shared.global [%0], [%1], 16;" :: "r"(dst), "l"(src));
}
#define CP_COMMIT() asm volatile("cp.async.commit_group;" ::: "memory")
#define CP_WAIT1()  asm volatile("cp.async.wait_group 1;" ::: "memory")

// B_NK = true : C[m][n] = sum_k A[m][k] * B[n][k]   (B [N,K] half)
// B_NK = false: C[m][n] = sum_k A[m][k] * B[k][n]   (B [K,N] half)
template <bool B_NK, int EPI, typename OutT>
__device__ __forceinline__ void gemm_body(
    const __half* __restrict__ A, long lda,
    const __half* __restrict__ B, long ldb,
    OutT* __restrict__ C, long ldc, int K)
{
    extern __shared__ char dynsm[];
    const uint32_t sraw = smem_u32(dynsm);
    const uint32_t sb   = (sraw + 127) & ~127u;

    const int t = threadIdx.x, lane = t & 31, warp = t >> 5;
    const int m0 = blockIdx.y * BM, n0 = blockIdx.x * BN;
    const int wm = (warp >> 1) * 64, wn = (warp & 1) * 64;
    const int fr = lane >> 2, fc = lane & 3;

    auto load_stage = [&](int slot, int k0) {
        const uint32_t ab = sb + slot * STAGE;
        const uint32_t bb = ab + A_STAGE;
#pragma unroll
        for (int it = 0; it < 8; it++) {
            int idx = t + it * NTHR;
            int row = idx >> 3, c = idx & 7;
            cp16(ab + row * 128 + ((c ^ (row & 7)) << 4),
                 A + (long)(m0 + row) * lda + k0 + c * 8);
        }
        if (B_NK) {
#pragma unroll
            for (int it = 0; it < 8; it++) {
                int idx = t + it * NTHR;
                int row = idx >> 3, c = idx & 7;
                cp16(bb + row * 128 + ((c ^ (row & 7)) << 4),
                     B + (long)(n0 + row) * ldb + k0 + c * 8);
            }
        } else {
#pragma unroll
            for (int it = 0; it < 8; it++) {
                int idx = t + it * NTHR;
                int k = idx >> 4, c = idx & 15;
                cp16(bb + k * 256 + ((c ^ (k & 7)) << 4),
                     B + (long)(k0 + k) * ldb + n0 + c * 8);
            }
        }
    };

    float acc[4][8][4];
#pragma unroll
    for (int i = 0; i < 4; i++)
#pragma unroll
        for (int j = 0; j < 8; j++)
#pragma unroll
            for (int r = 0; r < 4; r++) acc[i][j][r] = 0.f;

    float accS[4][4];   // row sums via ones-MMA (EPI==2 only)
    if (EPI == 2) {
#pragma unroll
        for (int i = 0; i < 4; i++)
#pragma unroll
            for (int r = 0; r < 4; r++) accS[i][r] = 0.f;
    }

    const int x7    = lane & 7;
    const int a_row = wm + ((lane >> 3) & 1) * 8 + x7;
    const int a_kc  = (lane >> 4) & 1;
    const int b_row = wn + ((lane >> 4) & 1) * 8 + x7;   // B_NK
    const int b_kc  = (lane >> 3) & 1;
    const int v_krow = ((lane >> 3) & 1) * 8 + x7;       // B_KN
    const int v_cof  = (lane >> 4) & 1;

    const int nT = K / TBK;
    load_stage(0, 0);   CP_COMMIT();
    load_stage(1, TBK); CP_COMMIT();

    for (int ti = 0; ti < nT; ti++) {
        CP_WAIT1();
        __syncthreads();

        const int pf = ti + 2;
        if (pf < nT) load_stage(pf % STAGES, pf * TBK);
        CP_COMMIT();

        const int slot = ti % STAGES;
        const uint32_t ab = sb + slot * STAGE;
        const uint32_t bb = ab + A_STAGE;

#pragma unroll
        for (int ks = 0; ks < 4; ks++) {      // 4 x K=16 per BK=64
            uint32_t af[4][4], bf[8][2];
#pragma unroll
            for (int im = 0; im < 4; im++) {
                uint32_t addr = ab + (a_row + im * 16) * 128 +
                                (((ks * 2 + a_kc) ^ x7) << 4);
                ldsm_x4(af[im][0], af[im][1], af[im][2], af[im][3], addr);
            }
            if (B_NK) {
#pragma unroll
                for (int p = 0; p < 4; p++) {
                    uint32_t addr = bb + (b_row + p * 16) * 128 +
                                    (((ks * 2 + b_kc) ^ x7) << 4);
                    ldsm_x4(bf[2 * p][0], bf[2 * p][1],
                            bf[2 * p + 1][0], bf[2 * p + 1][1], addr);
                }
            } else {
#pragma unroll
                for (int p = 0; p < 4; p++) {
                    int row_k = ks * 16 + v_krow;
                    int chunk = (wn >> 3) + 2 * p + v_cof;
                    uint32_t addr = bb + row_k * 256 + ((chunk ^ x7) << 4);
                    ldsm_x4_t(bf[2 * p][0], bf[2 * p][1],
                              bf[2 * p + 1][0], bf[2 * p + 1][1], addr);
                }
            }
#pragma unroll
            for (int im = 0; im < 4; im++)
#pragma unroll
                for (int in = 0; in < 8; in++)
                    mma_f16(acc[im][in], af[im][0], af[im][1], af[im][2], af[im][3],
                            bf[in][0], bf[in][1]);
            if (EPI == 2) {
#pragma unroll
                for (int im = 0; im < 4; im++)
                    mma_f16(accS[im], af[im][0], af[im][1], af[im][2], af[im][3],
                            ONES_H2, ONES_H2);
            }
        }
    }

    const float S = 0.03125f;   // 1/sqrt(1024)
#pragma unroll
    for (int im = 0; im < 4; im++) {
        float i0 = 1.f, i1 = 1.f;
        if (EPI == 2) { i0 = 1.0f / accS[im][0]; i1 = 1.0f / accS[im][2]; }
#pragma unroll
        for (int in = 0; in < 8; in++) {
            long row = m0 + wm + im * 16 + fr;
            long col = n0 + wn + in * 8 + 2 * fc;
            if (EPI == 0) {
                *(__half2*)((__half*)C + row * ldc + col) =
                    __floats2half2_rn(acc[im][in][0], acc[im][in][1]);
                *(__half2*)((__half*)C + (row + 8) * ldc + col) =
                    __floats2half2_rn(acc[im][in][2], acc[im][in][3]);
            } else if (EPI == 1) {
                *(__half2*)((__half*)C + row * ldc + col) =
                    __floats2half2_rn(__expf(acc[im][in][0] * S),
                                      __expf(acc[im][in][1] * S));
                *(__half2*)((__half*)C + (row + 8) * ldc + col) =
                    __floats2half2_rn(__expf(acc[im][in][2] * S),
                                      __expf(acc[im][in][3] * S));
            } else {
                *(float2*)((float*)C + row * ldc + col) =
                    make_float2(acc[im][in][0] * i0, acc[im][in][1] * i0);
                *(float2*)((float*)C + (row + 8) * ldc + col) =
                    make_float2(acc[im][in][2] * i1, acc[im][in][3] * i1);
            }
        }
    }
}

// ---------------------------------------------------------------------------
__global__ __launch_bounds__(256) void round_all_kernel(
    const float* __restrict__ x,  const float* __restrict__ Wq,
    const float* __restrict__ Wk, const float* __restrict__ Wv)
{
    const long i = ((long)blockIdx.x * 256 + threadIdx.x) * 8;
    const long NX = (long)MTOT * DM;
    const long NW = (long)DM * DM;
    const float* src; __half* dst; long off;
    if (i < NX)               { src = x;  dst = g_X;          off = i; }
    else if (i < NX + NW)     { src = Wq; dst = g_W;          off = i - NX; }
    else if (i < NX + 2 * NW) { src = Wk; dst = g_W + NW;     off = i - NX - NW; }
    else                      { src = Wv; dst = g_W + 2 * NW; off = i - NX - 2 * NW; }
    float4 v0 = *(const float4*)(src + off);
    float4 v1 = *(const float4*)(src + off + 4);
    __half2 h0 = __floats2half2_rn(v0.x, v0.y);
    __half2 h1 = __floats2half2_rn(v0.z, v0.w);
    __half2 h2 = __floats2half2_rn(v1.x, v1.y);
    __half2 h3 = __floats2half2_rn(v1.z, v1.w);
    uint4 u;
    u.x = *(uint32_t*)&h0; u.y = *(uint32_t*)&h1;
    u.z = *(uint32_t*)&h2; u.w = *(uint32_t*)&h3;
    *(uint4*)(dst + off) = u;
}

__global__ __launch_bounds__(NTHR, 2) void qkv_kernel()
{
    const __half* W = g_W + (long)blockIdx.z * DM * DM;
    __half* C = (blockIdx.z == 0) ? g_Q : (blockIdx.z == 1) ? g_K : g_V;
    gemm_body<true, 0, __half>(g_X, DM, W, DM, C, DM, DM);
}

// scores + fused softmax numerator: writes exp(QK^T/32) in fp16.
__global__ __launch_bounds__(NTHR, 2) void scores_kernel()
{
    const long b = blockIdx.z;
    gemm_body<true, 1, __half>(g_Q + b * (long)SEQ * DM, DM,
                               g_K + b * (long)SEQ * DM, DM,
                               g_Ph + b * (long)SEQ * SEQ, SEQ, DM);
}

// out = (e @ V) / rowsum(e); rowsum via ones-MMA in the mainloop.
__global__ __launch_bounds__(NTHR, 2) void out_kernel(float* __restrict__ out)
{
    const long b = blockIdx.z;
    gemm_body<false, 2, float>(g_Ph + b * (long)SEQ * SEQ, SEQ,
                               g_V + b * (long)SEQ * DM, DM,
                               out + b * (long)SEQ * DM, DM, SEQ);
}

// ---------------------------------------------------------------------------
extern "C" void kernel_launch(void* const* d_in, const int* in_sizes, int n_in,
                              void* d_out, int out_size)
{
    const float* x  = (const float*)d_in[0];
    const float* Wq = (const float*)d_in[1];
    const float* Wk = (const float*)d_in[2];
    const float* Wv = (const float*)d_in[3];
    float* out = (float*)d_out;

    static bool attr_done = false;
    if (!attr_done) {
        cudaFuncSetAttribute(qkv_kernel,    cudaFuncAttributeMaxDynamicSharedMemorySize, DYN_BYTES);
        cudaFuncSetAttribute(scores_kernel, cudaFuncAttributeMaxDynamicSharedMemorySize, DYN_BYTES);
        cudaFuncSetAttribute(out_kernel,    cudaFuncAttributeMaxDynamicSharedMemorySize, DYN_BYTES);
        attr_done = true;
    }

    dim3 blk(NTHR);
    const long totalElems = (long)MTOT * DM + 3L * DM * DM;
    round_all_kernel<<<(unsigned)(totalElems / 2048), 256>>>(x, Wq, Wk, Wv);

    qkv_kernel   <<<dim3(DM / BN,  MTOT / BM, 3),     blk, DYN_BYTES>>>();
    scores_kernel<<<dim3(SEQ / BN, SEQ / BM,  BATCH), blk, DYN_BYTES>>>();
    out_kernel   <<<dim3(DM / BN,  SEQ / BM,  BATCH), blk, DYN_BYTES>>>(out);
}